// round 3
// baseline (speedup 1.0000x reference)
#include <cuda_runtime.h>
#include <cuda_bf16.h>
#include <math.h>

#define IMG_H 2048
#define IMG_W 4096
#define IMG_C 3
#define ROW_BYTES (IMG_W * IMG_C * 4)   // 49152

// Precomputed separable tables.
__device__ float g_bx[IMG_W * 3];    // x-axis control weights
__device__ float g_rdy[IMG_H * 3];   // 5 * sum_y wy3[y]*D[0][y][x], per row
__device__ float g_rdx[IMG_H * 3];   // 5 * sum_y wy3[y]*D[1][y][x], per row

__device__ __forceinline__ float cubic_w(float t) {
    float at  = fabsf(t);
    float at2 = at * at;
    float at3 = at2 * at;
    const float a = -0.5f;
    float w_inner = (a + 2.0f) * at3 - (a + 3.0f) * at2 + 1.0f;
    float w_outer = a * at3 - 5.0f * a * at2 + 8.0f * a * at - 4.0f * a;
    return (at <= 1.0f) ? w_inner : ((at < 2.0f) ? w_outer : 0.0f);
}

__device__ __forceinline__ void ctrl_weights3(int i, float inv_scale, float w3[3]) {
    w3[0] = 0.0f; w3[1] = 0.0f; w3[2] = 0.0f;
    float u  = (float)i * inv_scale;
    int   i0 = (int)floorf(u);
    #pragma unroll
    for (int a = -1; a < 3; a++) {
        int   tap = i0 + a;
        float wv  = cubic_w(u - (float)tap);
        int   tc  = min(max(tap, 0), 2);
        w3[tc] += wv;
    }
}

__global__ void setup_tables(const float* __restrict__ dispc) {
    int i = blockIdx.x * blockDim.x + threadIdx.x;
    if (i < IMG_W) {
        float w3[3];
        ctrl_weights3(i, 2.0f / (float)(IMG_W - 1), w3);
        g_bx[i * 3 + 0] = w3[0];
        g_bx[i * 3 + 1] = w3[1];
        g_bx[i * 3 + 2] = w3[2];
    }
    if (i < IMG_H) {
        float w3[3];
        ctrl_weights3(i, 2.0f / (float)(IMG_H - 1), w3);
        #pragma unroll
        for (int x = 0; x < 3; x++) {
            float ry = w3[0] * dispc[0 * 3 + x] + w3[1] * dispc[3 + x] + w3[2] * dispc[6 + x];
            float rx = w3[0] * dispc[9 + x]     + w3[1] * dispc[12 + x] + w3[2] * dispc[15 + x];
            g_rdy[i * 3 + x] = 5.0f * ry;
            g_rdx[i * 3 + x] = 5.0f * rx;
        }
    }
}

// Closed-form Keys (a=-0.5) tap weights for frac t in [0,1).
__device__ __forceinline__ void keys_weights(float t, float w[4]) {
    float s  = 1.0f - t;
    float tt = t * t;
    float ss = s * s;
    w[0] = -0.5f * t * ss;
    w[1] = fmaf(fmaf(1.5f, t, -2.5f), tt, 1.0f);
    w[2] = fmaf(fmaf(1.5f, s, -2.5f), ss, 1.0f);
    w[3] = -0.5f * tt * s;
}

// Interior fast path: 4 rows, each gathered with 4 aligned LDG.128.
// Q = float offset of tap(-1) within the 16 loaded floats (0..3).
template<int Q>
__device__ __forceinline__ void gather4_vec(const char* __restrict__ ibase,
                                            const int rowoff[4], int base,
                                            const float wx[4], const float wy[4],
                                            float& acc0, float& acc1, float& acc2) {
    #pragma unroll
    for (int a = 0; a < 4; a++) {
        const float4* rp = (const float4*)(ibase + rowoff[a]) + base;
        float4 A = __ldg(rp + 0);
        float4 B = __ldg(rp + 1);
        float4 C = __ldg(rp + 2);
        float4 D = __ldg(rp + 3);
        float v[16] = {A.x, A.y, A.z, A.w, B.x, B.y, B.z, B.w,
                       C.x, C.y, C.z, C.w, D.x, D.y, D.z, D.w};
        float r0, r1, r2;
        r0 = wx[0] * v[Q + 0];
        r1 = wx[0] * v[Q + 1];
        r2 = wx[0] * v[Q + 2];
        r0 = fmaf(wx[1], v[Q + 3], r0);
        r1 = fmaf(wx[1], v[Q + 4], r1);
        r2 = fmaf(wx[1], v[Q + 5], r2);
        r0 = fmaf(wx[2], v[Q + 6], r0);
        r1 = fmaf(wx[2], v[Q + 7], r1);
        r2 = fmaf(wx[2], v[Q + 8], r2);
        r0 = fmaf(wx[3], v[Q + 9], r0);
        r1 = fmaf(wx[3], v[Q + 10], r1);
        r2 = fmaf(wx[3], v[Q + 11], r2);
        acc0 = fmaf(wy[a], r0, acc0);
        acc1 = fmaf(wy[a], r1, acc1);
        acc2 = fmaf(wy[a], r2, acc2);
    }
}

__global__ __launch_bounds__(256)
void elastic_warp_kernel(const float* __restrict__ img,
                         float* __restrict__ out) {
    int w = blockIdx.x * blockDim.x + threadIdx.x;
    int h = blockIdx.y * blockDim.y + threadIdx.y;

    // Displacement from separable tables: 6 FMAs.
    float bx0 = g_bx[w * 3 + 0], bx1 = g_bx[w * 3 + 1], bx2 = g_bx[w * 3 + 2];
    float dy = g_rdy[h * 3 + 0] * bx0 + g_rdy[h * 3 + 1] * bx1 + g_rdy[h * 3 + 2] * bx2;
    float dx = g_rdx[h * 3 + 0] * bx0 + g_rdx[h * 3 + 1] * bx1 + g_rdx[h * 3 + 2] * bx2;

    float yy = (float)h + dy;
    float xx = (float)w + dx;
    float iy0f = floorf(yy), ix0f = floorf(xx);
    int   iy0 = (int)iy0f,   ix0 = (int)ix0f;
    float fy = yy - iy0f,    fx = xx - ix0f;

    float wy[4], wx[4];
    keys_weights(fy, wy);
    keys_weights(fx, wx);

    const char* ibase = (const char*)img;
    float acc0 = 0.0f, acc1 = 0.0f, acc2 = 0.0f;

    bool interior = (ix0 >= 1) && (ix0 <= IMG_W - 4) && (iy0 >= 1) && (iy0 <= IMG_H - 3);

    if (interior) {
        int rowoff[4];
        #pragma unroll
        for (int a = 0; a < 4; a++) rowoff[a] = (iy0 - 1 + a) * ROW_BYTES;
        int p0   = (ix0 - 1) * 3;     // float index of tap(-1), channel 0
        int base = p0 >> 2;           // float4 index
        int q    = p0 & 3;
        switch (q) {
            case 0: gather4_vec<0>(ibase, rowoff, base, wx, wy, acc0, acc1, acc2); break;
            case 1: gather4_vec<1>(ibase, rowoff, base, wx, wy, acc0, acc1, acc2); break;
            case 2: gather4_vec<2>(ibase, rowoff, base, wx, wy, acc0, acc1, acc2); break;
            default: gather4_vec<3>(ibase, rowoff, base, wx, wy, acc0, acc1, acc2); break;
        }
    } else {
        // Border path: scalar gather with clamping.
        int coff[4];
        #pragma unroll
        for (int b = 0; b < 4; b++) {
            int tx = min(max(ix0 + b - 1, 0), IMG_W - 1);
            coff[b] = tx * (IMG_C * 4);
        }
        #pragma unroll
        for (int a = 0; a < 4; a++) {
            int ty = min(max(iy0 + a - 1, 0), IMG_H - 1);
            const char* rowp = ibase + (unsigned)ty * ROW_BYTES;
            float r0 = 0.0f, r1 = 0.0f, r2 = 0.0f;
            #pragma unroll
            for (int b = 0; b < 4; b++) {
                const float* p = (const float*)(rowp + coff[b]);
                float wv = wx[b];
                r0 = fmaf(wv, __ldg(p + 0), r0);
                r1 = fmaf(wv, __ldg(p + 1), r1);
                r2 = fmaf(wv, __ldg(p + 2), r2);
            }
            acc0 = fmaf(wy[a], r0, acc0);
            acc1 = fmaf(wy[a], r1, acc1);
            acc2 = fmaf(wy[a], r2, acc2);
        }
    }

    size_t o = ((size_t)h * IMG_W + (size_t)w) * IMG_C;
    out[o + 0] = acc0;
    out[o + 1] = acc1;
    out[o + 2] = acc2;
}

extern "C" void kernel_launch(void* const* d_in, const int* in_sizes, int n_in,
                              void* d_out, int out_size) {
    const float* img   = (const float*)d_in[0];   // (2048, 4096, 3) fp32
    const float* dispc = (const float*)d_in[1];   // (2, 3, 3) fp32
    float*       out   = (float*)d_out;

    setup_tables<<<(IMG_W + 255) / 256, 256>>>(dispc);

    dim3 block(64, 4, 1);
    dim3 grid(IMG_W / 64, IMG_H / 4, 1);
    elastic_warp_kernel<<<grid, block>>>(img, out);
}

// round 4
// speedup vs baseline: 1.0209x; 1.0209x over previous
#include <cuda_runtime.h>
#include <cuda_bf16.h>
#include <math.h>
#include <limits.h>

#define IMG_H 2048
#define IMG_W 4096
#define IMG_C 3
#define ROW_BYTES (IMG_W * IMG_C * 4)

#define BX 64
#define BY 4
#define NTHREADS (BX * BY)

#define R_MAX 12
#define C_MAX 80
#define PITCH (C_MAX * 3 + 1)   // 241 floats, padded

// Precomputed separable tables.
__device__ float g_bx[IMG_W * 3];    // x-axis control weights
__device__ float g_rdy[IMG_H * 3];   // 5 * sum_y wy3[y]*D[0][y][x], per row
__device__ float g_rdx[IMG_H * 3];   // 5 * sum_y wy3[y]*D[1][y][x], per row

__device__ __forceinline__ float cubic_w(float t) {
    float at  = fabsf(t);
    float at2 = at * at;
    float at3 = at2 * at;
    const float a = -0.5f;
    float w_inner = (a + 2.0f) * at3 - (a + 3.0f) * at2 + 1.0f;
    float w_outer = a * at3 - 5.0f * a * at2 + 8.0f * a * at - 4.0f * a;
    return (at <= 1.0f) ? w_inner : ((at < 2.0f) ? w_outer : 0.0f);
}

__device__ __forceinline__ void ctrl_weights3(int i, float inv_scale, float w3[3]) {
    w3[0] = 0.0f; w3[1] = 0.0f; w3[2] = 0.0f;
    float u  = (float)i * inv_scale;
    int   i0 = (int)floorf(u);
    #pragma unroll
    for (int a = -1; a < 3; a++) {
        int   tap = i0 + a;
        float wv  = cubic_w(u - (float)tap);
        int   tc  = min(max(tap, 0), 2);
        w3[tc] += wv;
    }
}

__global__ void setup_tables(const float* __restrict__ dispc) {
    int i = blockIdx.x * blockDim.x + threadIdx.x;
    if (i < IMG_W) {
        float w3[3];
        ctrl_weights3(i, 2.0f / (float)(IMG_W - 1), w3);
        g_bx[i * 3 + 0] = w3[0];
        g_bx[i * 3 + 1] = w3[1];
        g_bx[i * 3 + 2] = w3[2];
    }
    if (i < IMG_H) {
        float w3[3];
        ctrl_weights3(i, 2.0f / (float)(IMG_H - 1), w3);
        #pragma unroll
        for (int x = 0; x < 3; x++) {
            float ry = w3[0] * dispc[0 * 3 + x] + w3[1] * dispc[3 + x] + w3[2] * dispc[6 + x];
            float rx = w3[0] * dispc[9 + x]     + w3[1] * dispc[12 + x] + w3[2] * dispc[15 + x];
            g_rdy[i * 3 + x] = 5.0f * ry;
            g_rdx[i * 3 + x] = 5.0f * rx;
        }
    }
}

// Closed-form Keys (a=-0.5) tap weights for frac t in [0,1).
__device__ __forceinline__ void keys_weights(float t, float w[4]) {
    float s  = 1.0f - t;
    float tt = t * t;
    float ss = s * s;
    w[0] = -0.5f * t * ss;
    w[1] = fmaf(fmaf(1.5f, t, -2.5f), tt, 1.0f);
    w[2] = fmaf(fmaf(1.5f, s, -2.5f), ss, 1.0f);
    w[3] = -0.5f * tt * s;
}

// Fallback: direct-global scalar gather with clamping (R2 path).
__device__ __forceinline__ void gather_global(const float* __restrict__ img,
                                              int iy0, int ix0,
                                              const float wy[4], const float wx[4],
                                              float& acc0, float& acc1, float& acc2) {
    int coff[4];
    #pragma unroll
    for (int b = 0; b < 4; b++) {
        int tx = min(max(ix0 + b - 1, 0), IMG_W - 1);
        coff[b] = tx * (IMG_C * 4);
    }
    const char* ibase = (const char*)img;
    #pragma unroll
    for (int a = 0; a < 4; a++) {
        int ty = min(max(iy0 + a - 1, 0), IMG_H - 1);
        const char* rowp = ibase + (unsigned)ty * ROW_BYTES;
        float r0 = 0.0f, r1 = 0.0f, r2 = 0.0f;
        #pragma unroll
        for (int b = 0; b < 4; b++) {
            const float* p = (const float*)(rowp + coff[b]);
            float wv = wx[b];
            r0 = fmaf(wv, __ldg(p + 0), r0);
            r1 = fmaf(wv, __ldg(p + 1), r1);
            r2 = fmaf(wv, __ldg(p + 2), r2);
        }
        acc0 = fmaf(wy[a], r0, acc0);
        acc1 = fmaf(wy[a], r1, acc1);
        acc2 = fmaf(wy[a], r2, acc2);
    }
}

__global__ __launch_bounds__(NTHREADS)
void elastic_warp_kernel(const float* __restrict__ img,
                         float* __restrict__ out) {
    __shared__ float tile[R_MAX * PITCH];          // 11568 B
    __shared__ int s_minIy, s_maxIy, s_minIx, s_maxIx;

    int w = blockIdx.x * BX + threadIdx.x;
    int h = blockIdx.y * BY + threadIdx.y;
    int tid = threadIdx.y * BX + threadIdx.x;

    // Displacement from separable tables: 6 FMAs.
    float bx0 = g_bx[w * 3 + 0], bx1 = g_bx[w * 3 + 1], bx2 = g_bx[w * 3 + 2];
    float dy = g_rdy[h * 3 + 0] * bx0 + g_rdy[h * 3 + 1] * bx1 + g_rdy[h * 3 + 2] * bx2;
    float dx = g_rdx[h * 3 + 0] * bx0 + g_rdx[h * 3 + 1] * bx1 + g_rdx[h * 3 + 2] * bx2;

    float yy = (float)h + dy;
    float xx = (float)w + dx;
    float iy0f = floorf(yy), ix0f = floorf(xx);
    int   iy0 = (int)iy0f,   ix0 = (int)ix0f;
    float fy = yy - iy0f,    fx = xx - ix0f;

    float wy[4], wx[4];
    keys_weights(fy, wy);
    keys_weights(fx, wx);

    // --- block-wide min/max of (iy0, ix0) ---
    if (tid == 0) {
        s_minIy = INT_MAX; s_maxIy = INT_MIN;
        s_minIx = INT_MAX; s_maxIx = INT_MIN;
    }
    __syncthreads();
    {
        int wminy = __reduce_min_sync(0xffffffffu, iy0);
        int wmaxy = __reduce_max_sync(0xffffffffu, iy0);
        int wminx = __reduce_min_sync(0xffffffffu, ix0);
        int wmaxx = __reduce_max_sync(0xffffffffu, ix0);
        if ((tid & 31) == 0) {
            atomicMin(&s_minIy, wminy);
            atomicMax(&s_maxIy, wmaxy);
            atomicMin(&s_minIx, wminx);
            atomicMax(&s_maxIx, wmaxx);
        }
    }
    __syncthreads();

    int row_lo = min(max(s_minIy - 1, 0), IMG_H - 1);
    int row_hi = min(max(s_maxIy + 2, 0), IMG_H - 1);
    int col_lo = min(max(s_minIx - 1, 0), IMG_W - 1);
    int col_hi = min(max(s_maxIx + 2, 0), IMG_W - 1);
    int n_rows = row_hi - row_lo + 1;
    int n_cols = col_hi - col_lo + 1;

    float acc0 = 0.0f, acc1 = 0.0f, acc2 = 0.0f;

    if (n_rows <= R_MAX && n_cols <= C_MAX) {
        // --- stage window into smem, coalesced scalar loads ---
        int rowf = n_cols * 3;
        for (int r = 0; r < n_rows; r++) {
            const float* src = img + ((size_t)(row_lo + r) * IMG_W + col_lo) * IMG_C;
            float* dst = &tile[r * PITCH];
            for (int c = tid; c < rowf; c += NTHREADS)
                dst[c] = __ldg(src + c);
        }
        __syncthreads();

        // --- gather 4x4 taps from smem ---
        int sroff[4], scoff[4];
        #pragma unroll
        for (int a = 0; a < 4; a++) {
            int ty = min(max(iy0 + a - 1, 0), IMG_H - 1);
            sroff[a] = (ty - row_lo) * PITCH;
        }
        #pragma unroll
        for (int b = 0; b < 4; b++) {
            int tx = min(max(ix0 + b - 1, 0), IMG_W - 1);
            scoff[b] = (tx - col_lo) * 3;
        }
        #pragma unroll
        for (int a = 0; a < 4; a++) {
            const float* rowp = &tile[sroff[a]];
            float r0 = 0.0f, r1 = 0.0f, r2 = 0.0f;
            #pragma unroll
            for (int b = 0; b < 4; b++) {
                const float* p = rowp + scoff[b];
                float wv = wx[b];
                r0 = fmaf(wv, p[0], r0);
                r1 = fmaf(wv, p[1], r1);
                r2 = fmaf(wv, p[2], r2);
            }
            acc0 = fmaf(wy[a], r0, acc0);
            acc1 = fmaf(wy[a], r1, acc1);
            acc2 = fmaf(wy[a], r2, acc2);
        }
    } else {
        // Block-uniform fallback (no syncs inside): direct global gather.
        gather_global(img, iy0, ix0, wy, wx, acc0, acc1, acc2);
    }

    size_t o = ((size_t)h * IMG_W + (size_t)w) * IMG_C;
    out[o + 0] = acc0;
    out[o + 1] = acc1;
    out[o + 2] = acc2;
}

extern "C" void kernel_launch(void* const* d_in, const int* in_sizes, int n_in,
                              void* d_out, int out_size) {
    const float* img   = (const float*)d_in[0];   // (2048, 4096, 3) fp32
    const float* dispc = (const float*)d_in[1];   // (2, 3, 3) fp32
    float*       out   = (float*)d_out;

    setup_tables<<<(IMG_W + 255) / 256, 256>>>(dispc);

    dim3 block(BX, BY, 1);
    dim3 grid(IMG_W / BX, IMG_H / BY, 1);
    elastic_warp_kernel<<<grid, block>>>(img, out);
}

// round 5
// speedup vs baseline: 1.6088x; 1.5759x over previous
#include <cuda_runtime.h>
#include <cuda_bf16.h>
#include <math.h>

#define IMG_H 2048
#define IMG_W 4096
#define IMG_C 3
#define ROW_BYTES (IMG_W * IMG_C * 4)
#define ROW_F4 (IMG_W * IMG_C / 4)          // 3072 float4 per image row
#define TOTAL_F4 (IMG_H * ROW_F4)

#define BX 64
#define BY 4
#define NTHREADS (BX * BY)
#define WARPS_PER_BLOCK (NTHREADS / 32)

#define TILE_ROWS 6
#define TILE_PITCH 132                       // floats per staged row (128 + pad, 16B-mult)
#define TILE_F (TILE_ROWS * TILE_PITCH)      // 792 floats per warp

// Precomputed separable tables.
__device__ float g_bx[IMG_W * 3];    // x-axis control weights
__device__ float g_rdy[IMG_H * 3];   // 5 * sum_y wy3[y]*D[0][y][x]
__device__ float g_rdx[IMG_H * 3];   // 5 * sum_y wy3[y]*D[1][y][x]

__device__ __forceinline__ float cubic_w(float t) {
    float at  = fabsf(t);
    float at2 = at * at;
    float at3 = at2 * at;
    const float a = -0.5f;
    float w_inner = (a + 2.0f) * at3 - (a + 3.0f) * at2 + 1.0f;
    float w_outer = a * at3 - 5.0f * a * at2 + 8.0f * a * at - 4.0f * a;
    return (at <= 1.0f) ? w_inner : ((at < 2.0f) ? w_outer : 0.0f);
}

__device__ __forceinline__ void ctrl_weights3(int i, float inv_scale, float w3[3]) {
    w3[0] = 0.0f; w3[1] = 0.0f; w3[2] = 0.0f;
    float u  = (float)i * inv_scale;
    int   i0 = (int)floorf(u);
    #pragma unroll
    for (int a = -1; a < 3; a++) {
        int   tap = i0 + a;
        float wv  = cubic_w(u - (float)tap);
        int   tc  = min(max(tap, 0), 2);
        w3[tc] += wv;
    }
}

__global__ void setup_tables(const float* __restrict__ dispc) {
    int i = blockIdx.x * blockDim.x + threadIdx.x;
    if (i < IMG_W) {
        float w3[3];
        ctrl_weights3(i, 2.0f / (float)(IMG_W - 1), w3);
        g_bx[i * 3 + 0] = w3[0];
        g_bx[i * 3 + 1] = w3[1];
        g_bx[i * 3 + 2] = w3[2];
    }
    if (i < IMG_H) {
        float w3[3];
        ctrl_weights3(i, 2.0f / (float)(IMG_H - 1), w3);
        #pragma unroll
        for (int x = 0; x < 3; x++) {
            float ry = w3[0] * dispc[0 * 3 + x] + w3[1] * dispc[3 + x] + w3[2] * dispc[6 + x];
            float rx = w3[0] * dispc[9 + x]     + w3[1] * dispc[12 + x] + w3[2] * dispc[15 + x];
            g_rdy[i * 3 + x] = 5.0f * ry;
            g_rdx[i * 3 + x] = 5.0f * rx;
        }
    }
}

// Closed-form Keys (a=-0.5) tap weights for frac t in [0,1).
__device__ __forceinline__ void keys_weights(float t, float w[4]) {
    float s  = 1.0f - t;
    float tt = t * t;
    float ss = s * s;
    w[0] = -0.5f * t * ss;
    w[1] = fmaf(fmaf(1.5f, t, -2.5f), tt, 1.0f);
    w[2] = fmaf(fmaf(1.5f, s, -2.5f), ss, 1.0f);
    w[3] = -0.5f * tt * s;
}

// Fallback: direct-global scalar gather with clamping (R2 path).
__device__ __forceinline__ void gather_global(const float* __restrict__ img,
                                              int iy0, int ix0,
                                              const float wy[4], const float wx[4],
                                              float& acc0, float& acc1, float& acc2) {
    int coff[4];
    #pragma unroll
    for (int b = 0; b < 4; b++) {
        int tx = min(max(ix0 + b - 1, 0), IMG_W - 1);
        coff[b] = tx * (IMG_C * 4);
    }
    const char* ibase = (const char*)img;
    #pragma unroll
    for (int a = 0; a < 4; a++) {
        int ty = min(max(iy0 + a - 1, 0), IMG_H - 1);
        const char* rowp = ibase + (unsigned)ty * ROW_BYTES;
        float r0 = 0.0f, r1 = 0.0f, r2 = 0.0f;
        #pragma unroll
        for (int b = 0; b < 4; b++) {
            const float* p = (const float*)(rowp + coff[b]);
            float wv = wx[b];
            r0 = fmaf(wv, __ldg(p + 0), r0);
            r1 = fmaf(wv, __ldg(p + 1), r1);
            r2 = fmaf(wv, __ldg(p + 2), r2);
        }
        acc0 = fmaf(wy[a], r0, acc0);
        acc1 = fmaf(wy[a], r1, acc1);
        acc2 = fmaf(wy[a], r2, acc2);
    }
}

__global__ __launch_bounds__(NTHREADS)
void elastic_warp_kernel(const float* __restrict__ img,
                         float* __restrict__ out) {
    __shared__ float tile[WARPS_PER_BLOCK * TILE_F];   // 8 * 792 * 4 = 25344 B

    int w    = blockIdx.x * BX + threadIdx.x;
    int h    = blockIdx.y * BY + threadIdx.y;
    int tid  = threadIdx.y * BX + threadIdx.x;
    int lane = tid & 31;
    int wid  = tid >> 5;

    // Displacement from separable tables: 6 FMAs.
    float bx0 = g_bx[w * 3 + 0], bx1 = g_bx[w * 3 + 1], bx2 = g_bx[w * 3 + 2];
    float dy = g_rdy[h * 3 + 0] * bx0 + g_rdy[h * 3 + 1] * bx1 + g_rdy[h * 3 + 2] * bx2;
    float dx = g_rdx[h * 3 + 0] * bx0 + g_rdx[h * 3 + 1] * bx1 + g_rdx[h * 3 + 2] * bx2;

    float yy = (float)h + dy;
    float xx = (float)w + dx;
    float iy0f = floorf(yy), ix0f = floorf(xx);
    int   iy0 = (int)iy0f,   ix0 = (int)ix0f;
    float fy = yy - iy0f,    fx = xx - ix0f;

    float wy[4], wx[4];
    keys_weights(fy, wy);
    keys_weights(fx, wx);

    // Warp-uniform window bounds (single-instruction redux).
    int wminy = __reduce_min_sync(0xffffffffu, iy0);
    int wmaxy = __reduce_max_sync(0xffffffffu, iy0);
    int wminx = __reduce_min_sync(0xffffffffu, ix0);
    int wmaxx = __reduce_max_sync(0xffffffffu, ix0);

    int row_lo = min(max(wminy - 1, 0), IMG_H - 1);
    int row_hi = min(max(wmaxy + 2, 0), IMG_H - 1);
    int col_lo = min(max(wminx - 1, 0), IMG_W - 1) & ~3;   // 16B-align the float window
    int col_hi = min(max(wmaxx + 2, 0), IMG_W - 1);

    float acc0 = 0.0f, acc1 = 0.0f, acc2 = 0.0f;

    bool fast = (row_hi - row_lo <= TILE_ROWS - 1) && (col_hi - col_lo <= 41);

    if (fast) {
        float* wt = &tile[wid * TILE_F];
        const float4* img4 = (const float4*)img;
        int base4 = (col_lo * 3) >> 2;   // col_lo mult of 4 -> col_lo*3 mult of 12 (int, 16B-aligned)

        // Stage 6 rows x 128 floats, one coalesced LDG.128 + STS.128 per row per lane.
        #pragma unroll
        for (int r = 0; r < TILE_ROWS; r++) {
            int gr   = min(row_lo + r, IMG_H - 1);
            int idx4 = min(gr * ROW_F4 + base4 + lane, TOTAL_F4 - 1);
            float4 v = __ldg(img4 + idx4);
            *(float4*)(wt + r * TILE_PITCH + lane * 4) = v;
        }
        __syncwarp();

        // Gather 4x4 taps from smem (stride-3 lanes: conflict-free).
        int sr[4], sc[4];
        #pragma unroll
        for (int a = 0; a < 4; a++) {
            int ty = min(max(iy0 + a - 1, 0), IMG_H - 1);
            sr[a] = (ty - row_lo) * TILE_PITCH;
        }
        #pragma unroll
        for (int b = 0; b < 4; b++) {
            int tx = min(max(ix0 + b - 1, 0), IMG_W - 1);
            sc[b] = (tx - col_lo) * 3;
        }
        #pragma unroll
        for (int a = 0; a < 4; a++) {
            const float* rowp = wt + sr[a];
            float r0 = 0.0f, r1 = 0.0f, r2 = 0.0f;
            #pragma unroll
            for (int b = 0; b < 4; b++) {
                const float* p = rowp + sc[b];
                float wv = wx[b];
                r0 = fmaf(wv, p[0], r0);
                r1 = fmaf(wv, p[1], r1);
                r2 = fmaf(wv, p[2], r2);
            }
            acc0 = fmaf(wy[a], r0, acc0);
            acc1 = fmaf(wy[a], r1, acc1);
            acc2 = fmaf(wy[a], r2, acc2);
        }
    } else {
        // Warp-uniform fallback: direct global gather (no syncs needed).
        gather_global(img, iy0, ix0, wy, wx, acc0, acc1, acc2);
    }

    size_t o = ((size_t)h * IMG_W + (size_t)w) * IMG_C;
    out[o + 0] = acc0;
    out[o + 1] = acc1;
    out[o + 2] = acc2;
}

extern "C" void kernel_launch(void* const* d_in, const int* in_sizes, int n_in,
                              void* d_out, int out_size) {
    const float* img   = (const float*)d_in[0];   // (2048, 4096, 3) fp32
    const float* dispc = (const float*)d_in[1];   // (2, 3, 3) fp32
    float*       out   = (float*)d_out;

    setup_tables<<<(IMG_W + 255) / 256, 256>>>(dispc);

    dim3 block(BX, BY, 1);
    dim3 grid(IMG_W / BX, IMG_H / BY, 1);
    elastic_warp_kernel<<<grid, block>>>(img, out);
}

// round 6
// speedup vs baseline: 2.3056x; 1.4332x over previous
#include <cuda_runtime.h>
#include <cuda_bf16.h>
#include <math.h>

#define IMG_H 2048
#define IMG_W 4096
#define IMG_C 3
#define ROW_BYTES (IMG_W * IMG_C * 4)

#define BX 64
#define BY 4
#define NTHREADS (BX * BY)
#define PX_PER_THREAD 4   // vertical quad

// Precomputed separable tables.
__device__ float g_bx[IMG_W * 3];    // x-axis control weights
__device__ float g_rdy[IMG_H * 3];   // 5 * sum_y wy3[y]*D[0][y][x]
__device__ float g_rdx[IMG_H * 3];   // 5 * sum_y wy3[y]*D[1][y][x]

__device__ __forceinline__ float cubic_w(float t) {
    float at  = fabsf(t);
    float at2 = at * at;
    float at3 = at2 * at;
    const float a = -0.5f;
    float w_inner = (a + 2.0f) * at3 - (a + 3.0f) * at2 + 1.0f;
    float w_outer = a * at3 - 5.0f * a * at2 + 8.0f * a * at - 4.0f * a;
    return (at <= 1.0f) ? w_inner : ((at < 2.0f) ? w_outer : 0.0f);
}

__device__ __forceinline__ void ctrl_weights3(int i, float inv_scale, float w3[3]) {
    w3[0] = 0.0f; w3[1] = 0.0f; w3[2] = 0.0f;
    float u  = (float)i * inv_scale;
    int   i0 = (int)floorf(u);
    #pragma unroll
    for (int a = -1; a < 3; a++) {
        int   tap = i0 + a;
        float wv  = cubic_w(u - (float)tap);
        int   tc  = min(max(tap, 0), 2);
        w3[tc] += wv;
    }
}

__global__ void setup_tables(const float* __restrict__ dispc) {
    int i = blockIdx.x * blockDim.x + threadIdx.x;
    if (i < IMG_W) {
        float w3[3];
        ctrl_weights3(i, 2.0f / (float)(IMG_W - 1), w3);
        g_bx[i * 3 + 0] = w3[0];
        g_bx[i * 3 + 1] = w3[1];
        g_bx[i * 3 + 2] = w3[2];
    }
    if (i < IMG_H) {
        float w3[3];
        ctrl_weights3(i, 2.0f / (float)(IMG_H - 1), w3);
        #pragma unroll
        for (int x = 0; x < 3; x++) {
            float ry = w3[0] * dispc[0 * 3 + x] + w3[1] * dispc[3 + x] + w3[2] * dispc[6 + x];
            float rx = w3[0] * dispc[9 + x]     + w3[1] * dispc[12 + x] + w3[2] * dispc[15 + x];
            g_rdy[i * 3 + x] = 5.0f * ry;
            g_rdx[i * 3 + x] = 5.0f * rx;
        }
    }
}

// Closed-form Keys (a=-0.5) tap weights for frac t in [0,1).
__device__ __forceinline__ void keys_weights(float t, float w[4]) {
    float s  = 1.0f - t;
    float tt = t * t;
    float ss = s * s;
    w[0] = -0.5f * t * ss;
    w[1] = fmaf(fmaf(1.5f, t, -2.5f), tt, 1.0f);
    w[2] = fmaf(fmaf(1.5f, s, -2.5f), ss, 1.0f);
    w[3] = -0.5f * tt * s;
}

// Independent per-pixel gather with clamping (R2 path).
__device__ __forceinline__ void gather_global(const float* __restrict__ img,
                                              int iy0, int ix0,
                                              const float wy[4], const float wx[4],
                                              float& acc0, float& acc1, float& acc2) {
    int coff[4];
    #pragma unroll
    for (int b = 0; b < 4; b++) {
        int tx = min(max(ix0 + b - 1, 0), IMG_W - 1);
        coff[b] = tx * (IMG_C * 4);
    }
    const char* ibase = (const char*)img;
    #pragma unroll
    for (int a = 0; a < 4; a++) {
        int ty = min(max(iy0 + a - 1, 0), IMG_H - 1);
        const char* rowp = ibase + (unsigned)ty * ROW_BYTES;
        float r0 = 0.0f, r1 = 0.0f, r2 = 0.0f;
        #pragma unroll
        for (int b = 0; b < 4; b++) {
            const float* p = (const float*)(rowp + coff[b]);
            float wv = wx[b];
            r0 = fmaf(wv, __ldg(p + 0), r0);
            r1 = fmaf(wv, __ldg(p + 1), r1);
            r2 = fmaf(wv, __ldg(p + 2), r2);
        }
        acc0 = fmaf(wy[a], r0, acc0);
        acc1 = fmaf(wy[a], r1, acc1);
        acc2 = fmaf(wy[a], r2, acc2);
    }
}

__global__ __launch_bounds__(NTHREADS)
void elastic_warp_kernel(const float* __restrict__ img,
                         float* __restrict__ out) {
    int w  = blockIdx.x * BX + threadIdx.x;
    int h0 = (blockIdx.y * BY + threadIdx.y) * PX_PER_THREAD;

    float bx0 = g_bx[w * 3 + 0], bx1 = g_bx[w * 3 + 1], bx2 = g_bx[w * 3 + 2];

    int   iy0[4], ix0[4];
    float wy[4][4], wx[4][4];

    #pragma unroll
    for (int p = 0; p < PX_PER_THREAD; p++) {
        int h = h0 + p;
        float dy = g_rdy[h * 3 + 0] * bx0 + g_rdy[h * 3 + 1] * bx1 + g_rdy[h * 3 + 2] * bx2;
        float dx = g_rdx[h * 3 + 0] * bx0 + g_rdx[h * 3 + 1] * bx1 + g_rdx[h * 3 + 2] * bx2;
        float yy = (float)h + dy;
        float xx = (float)w + dx;
        float iy0f = floorf(yy), ix0f = floorf(xx);
        iy0[p] = (int)iy0f;
        ix0[p] = (int)ix0f;
        keys_weights(yy - iy0f, wy[p]);
        keys_weights(xx - ix0f, wx[p]);
    }

    float acc[4][3];
    #pragma unroll
    for (int p = 0; p < PX_PER_THREAD; p++)
        acc[p][0] = acc[p][1] = acc[p][2] = 0.0f;

    bool fast = (ix0[1] == ix0[0]) && (ix0[2] == ix0[0]) && (ix0[3] == ix0[0]) &&
                (iy0[1] == iy0[0] + 1) && (iy0[2] == iy0[0] + 2) && (iy0[3] == iy0[0] + 3);

    const char* ibase = (const char*)img;

    if (fast) {
        // Shared 7-row x 4-col tap window.
        int coff[4];
        #pragma unroll
        for (int b = 0; b < 4; b++) {
            int tx = min(max(ix0[0] + b - 1, 0), IMG_W - 1);
            coff[b] = tx * (IMG_C * 4);
        }
        #pragma unroll
        for (int a = 0; a < 7; a++) {
            int ty = min(max(iy0[0] + a - 1, 0), IMG_H - 1);
            const char* rowp = ibase + (unsigned)ty * ROW_BYTES;
            float v[12];
            #pragma unroll
            for (int b = 0; b < 4; b++) {
                const float* p = (const float*)(rowp + coff[b]);
                v[b * 3 + 0] = __ldg(p + 0);
                v[b * 3 + 1] = __ldg(p + 1);
                v[b * 3 + 2] = __ldg(p + 2);
            }
            // Pixels p with 0 <= a-p <= 3 use this row as tap k=a-p.
            #pragma unroll
            for (int p = 0; p < PX_PER_THREAD; p++) {
                int k = a - p;
                if (k >= 0 && k < 4) {
                    const float* wxp = wx[p];
                    float r0 = wxp[0] * v[0];
                    float r1 = wxp[0] * v[1];
                    float r2 = wxp[0] * v[2];
                    r0 = fmaf(wxp[1], v[3], r0);
                    r1 = fmaf(wxp[1], v[4], r1);
                    r2 = fmaf(wxp[1], v[5], r2);
                    r0 = fmaf(wxp[2], v[6], r0);
                    r1 = fmaf(wxp[2], v[7], r1);
                    r2 = fmaf(wxp[2], v[8], r2);
                    r0 = fmaf(wxp[3], v[9], r0);
                    r1 = fmaf(wxp[3], v[10], r1);
                    r2 = fmaf(wxp[3], v[11], r2);
                    float wk = wy[p][k];
                    acc[p][0] = fmaf(wk, r0, acc[p][0]);
                    acc[p][1] = fmaf(wk, r1, acc[p][1]);
                    acc[p][2] = fmaf(wk, r2, acc[p][2]);
                }
            }
        }
    } else {
        #pragma unroll
        for (int p = 0; p < PX_PER_THREAD; p++)
            gather_global(img, iy0[p], ix0[p], wy[p], wx[p],
                          acc[p][0], acc[p][1], acc[p][2]);
    }

    #pragma unroll
    for (int p = 0; p < PX_PER_THREAD; p++) {
        size_t o = ((size_t)(h0 + p) * IMG_W + (size_t)w) * IMG_C;
        out[o + 0] = acc[p][0];
        out[o + 1] = acc[p][1];
        out[o + 2] = acc[p][2];
    }
}

extern "C" void kernel_launch(void* const* d_in, const int* in_sizes, int n_in,
                              void* d_out, int out_size) {
    const float* img   = (const float*)d_in[0];   // (2048, 4096, 3) fp32
    const float* dispc = (const float*)d_in[1];   // (2, 3, 3) fp32
    float*       out   = (float*)d_out;

    setup_tables<<<(IMG_W + 255) / 256, 256>>>(dispc);

    dim3 block(BX, BY, 1);
    dim3 grid(IMG_W / BX, IMG_H / (BY * PX_PER_THREAD), 1);
    elastic_warp_kernel<<<grid, block>>>(img, out);
}

// round 7
// speedup vs baseline: 2.5240x; 1.0947x over previous
#include <cuda_runtime.h>
#include <cuda_bf16.h>
#include <math.h>

#define IMG_H 2048
#define IMG_W 4096
#define IMG_C 3
#define ROW_BYTES (IMG_W * IMG_C * 4)

#define BX 64
#define BY 4
#define NTHREADS (BX * BY)
#define PX_PER_THREAD 4   // vertical quad

// Precomputed separable tables.
__device__ float g_bx[IMG_W * 3];    // x-axis control weights
__device__ float g_rdy[IMG_H * 3];   // 5 * sum_y wy3[y]*D[0][y][x]
__device__ float g_rdx[IMG_H * 3];   // 5 * sum_y wy3[y]*D[1][y][x]

__device__ __forceinline__ float cubic_w(float t) {
    float at  = fabsf(t);
    float at2 = at * at;
    float at3 = at2 * at;
    const float a = -0.5f;
    float w_inner = (a + 2.0f) * at3 - (a + 3.0f) * at2 + 1.0f;
    float w_outer = a * at3 - 5.0f * a * at2 + 8.0f * a * at - 4.0f * a;
    return (at <= 1.0f) ? w_inner : ((at < 2.0f) ? w_outer : 0.0f);
}

__device__ __forceinline__ void ctrl_weights3(int i, float inv_scale, float w3[3]) {
    w3[0] = 0.0f; w3[1] = 0.0f; w3[2] = 0.0f;
    float u  = (float)i * inv_scale;
    int   i0 = (int)floorf(u);
    #pragma unroll
    for (int a = -1; a < 3; a++) {
        int   tap = i0 + a;
        float wv  = cubic_w(u - (float)tap);
        int   tc  = min(max(tap, 0), 2);
        w3[tc] += wv;
    }
}

__global__ void setup_tables(const float* __restrict__ dispc) {
    int i = blockIdx.x * blockDim.x + threadIdx.x;
    if (i < IMG_W) {
        float w3[3];
        ctrl_weights3(i, 2.0f / (float)(IMG_W - 1), w3);
        g_bx[i * 3 + 0] = w3[0];
        g_bx[i * 3 + 1] = w3[1];
        g_bx[i * 3 + 2] = w3[2];
    }
    if (i < IMG_H) {
        float w3[3];
        ctrl_weights3(i, 2.0f / (float)(IMG_H - 1), w3);
        #pragma unroll
        for (int x = 0; x < 3; x++) {
            float ry = w3[0] * dispc[0 * 3 + x] + w3[1] * dispc[3 + x] + w3[2] * dispc[6 + x];
            float rx = w3[0] * dispc[9 + x]     + w3[1] * dispc[12 + x] + w3[2] * dispc[15 + x];
            g_rdy[i * 3 + x] = 5.0f * ry;
            g_rdx[i * 3 + x] = 5.0f * rx;
        }
    }
}

// Closed-form Keys (a=-0.5) tap weights for frac t in [0,1).
__device__ __forceinline__ void keys_weights(float t, float w[4]) {
    float s  = 1.0f - t;
    float tt = t * t;
    float ss = s * s;
    w[0] = -0.5f * t * ss;
    w[1] = fmaf(fmaf(1.5f, t, -2.5f), tt, 1.0f);
    w[2] = fmaf(fmaf(1.5f, s, -2.5f), ss, 1.0f);
    w[3] = -0.5f * tt * s;
}

// Rare path: full per-pixel recompute + clamped gather + store for the quad.
// __noinline__ so its register state never inflates the hot path.
__device__ __noinline__ void quad_fallback(const float* __restrict__ img,
                                           float* __restrict__ out,
                                           int w, int h0,
                                           float bx0, float bx1, float bx2) {
    const char* ibase = (const char*)img;
    for (int p = 0; p < PX_PER_THREAD; p++) {
        int h = h0 + p;
        float dy = g_rdy[h * 3 + 0] * bx0 + g_rdy[h * 3 + 1] * bx1 + g_rdy[h * 3 + 2] * bx2;
        float dx = g_rdx[h * 3 + 0] * bx0 + g_rdx[h * 3 + 1] * bx1 + g_rdx[h * 3 + 2] * bx2;
        float yy = (float)h + dy;
        float xx = (float)w + dx;
        float iy0f = floorf(yy), ix0f = floorf(xx);
        int   iy0 = (int)iy0f,   ix0 = (int)ix0f;
        float wy[4], wx[4];
        keys_weights(yy - iy0f, wy);
        keys_weights(xx - ix0f, wx);

        int coff[4];
        #pragma unroll
        for (int b = 0; b < 4; b++) {
            int tx = min(max(ix0 + b - 1, 0), IMG_W - 1);
            coff[b] = tx * (IMG_C * 4);
        }
        float acc0 = 0.0f, acc1 = 0.0f, acc2 = 0.0f;
        #pragma unroll
        for (int a = 0; a < 4; a++) {
            int ty = min(max(iy0 + a - 1, 0), IMG_H - 1);
            const char* rowp = ibase + (unsigned)ty * ROW_BYTES;
            float r0 = 0.0f, r1 = 0.0f, r2 = 0.0f;
            #pragma unroll
            for (int b = 0; b < 4; b++) {
                const float* pp = (const float*)(rowp + coff[b]);
                float wv = wx[b];
                r0 = fmaf(wv, __ldg(pp + 0), r0);
                r1 = fmaf(wv, __ldg(pp + 1), r1);
                r2 = fmaf(wv, __ldg(pp + 2), r2);
            }
            acc0 = fmaf(wy[a], r0, acc0);
            acc1 = fmaf(wy[a], r1, acc1);
            acc2 = fmaf(wy[a], r2, acc2);
        }
        size_t o = ((size_t)h * IMG_W + (size_t)w) * IMG_C;
        out[o + 0] = acc0;
        out[o + 1] = acc1;
        out[o + 2] = acc2;
    }
}

__global__ __launch_bounds__(NTHREADS, 4)
void elastic_warp_kernel(const float* __restrict__ img,
                         float* __restrict__ out) {
    int w  = blockIdx.x * BX + threadIdx.x;
    int h0 = (blockIdx.y * BY + threadIdx.y) * PX_PER_THREAD;

    float bx0 = g_bx[w * 3 + 0], bx1 = g_bx[w * 3 + 1], bx2 = g_bx[w * 3 + 2];

    // Compute coordinates; track quad pattern with a running bool.
    float fy[4], fx[4];
    int iy00 = 0, ix00 = 0;
    bool fast = true;
    #pragma unroll
    for (int p = 0; p < PX_PER_THREAD; p++) {
        int h = h0 + p;
        float dy = g_rdy[h * 3 + 0] * bx0 + g_rdy[h * 3 + 1] * bx1 + g_rdy[h * 3 + 2] * bx2;
        float dx = g_rdx[h * 3 + 0] * bx0 + g_rdx[h * 3 + 1] * bx1 + g_rdx[h * 3 + 2] * bx2;
        float yy = (float)h + dy;
        float xx = (float)w + dx;
        float iy0f = floorf(yy), ix0f = floorf(xx);
        int   iy0 = (int)iy0f,   ix0 = (int)ix0f;
        fy[p] = yy - iy0f;
        fx[p] = xx - ix0f;
        if (p == 0) { iy00 = iy0; ix00 = ix0; }
        else        { fast = fast && (ix0 == ix00) && (iy0 == iy00 + p); }
    }

    if (!fast) {
        quad_fallback(img, out, w, h0, bx0, bx1, bx2);
        return;
    }

    float wy[4][4], wx[4][4];
    #pragma unroll
    for (int p = 0; p < PX_PER_THREAD; p++) {
        keys_weights(fy[p], wy[p]);
        keys_weights(fx[p], wx[p]);
    }

    float acc[4][3];
    #pragma unroll
    for (int p = 0; p < PX_PER_THREAD; p++)
        acc[p][0] = acc[p][1] = acc[p][2] = 0.0f;

    const char* ibase = (const char*)img;
    int coff[4];
    #pragma unroll
    for (int b = 0; b < 4; b++) {
        int tx = min(max(ix00 + b - 1, 0), IMG_W - 1);
        coff[b] = tx * (IMG_C * 4);
    }

    #pragma unroll
    for (int a = 0; a < 7; a++) {
        int ty = min(max(iy00 + a - 1, 0), IMG_H - 1);
        const char* rowp = ibase + (unsigned)ty * ROW_BYTES;
        float v[12];
        #pragma unroll
        for (int b = 0; b < 4; b++) {
            const float* p = (const float*)(rowp + coff[b]);
            v[b * 3 + 0] = __ldg(p + 0);
            v[b * 3 + 1] = __ldg(p + 1);
            v[b * 3 + 2] = __ldg(p + 2);
        }
        // Pixel p uses row a as its tap k = a - p when 0 <= k < 4.
        #pragma unroll
        for (int p = 0; p < PX_PER_THREAD; p++) {
            int k = a - p;
            if (k >= 0 && k < 4) {
                const float* wxp = wx[p];
                float r0 = wxp[0] * v[0];
                float r1 = wxp[0] * v[1];
                float r2 = wxp[0] * v[2];
                r0 = fmaf(wxp[1], v[3], r0);
                r1 = fmaf(wxp[1], v[4], r1);
                r2 = fmaf(wxp[1], v[5], r2);
                r0 = fmaf(wxp[2], v[6], r0);
                r1 = fmaf(wxp[2], v[7], r1);
                r2 = fmaf(wxp[2], v[8], r2);
                r0 = fmaf(wxp[3], v[9], r0);
                r1 = fmaf(wxp[3], v[10], r1);
                r2 = fmaf(wxp[3], v[11], r2);
                float wk = wy[p][k];
                acc[p][0] = fmaf(wk, r0, acc[p][0]);
                acc[p][1] = fmaf(wk, r1, acc[p][1]);
                acc[p][2] = fmaf(wk, r2, acc[p][2]);
            }
        }
    }

    #pragma unroll
    for (int p = 0; p < PX_PER_THREAD; p++) {
        size_t o = ((size_t)(h0 + p) * IMG_W + (size_t)w) * IMG_C;
        out[o + 0] = acc[p][0];
        out[o + 1] = acc[p][1];
        out[o + 2] = acc[p][2];
    }
}

extern "C" void kernel_launch(void* const* d_in, const int* in_sizes, int n_in,
                              void* d_out, int out_size) {
    const float* img   = (const float*)d_in[0];   // (2048, 4096, 3) fp32
    const float* dispc = (const float*)d_in[1];   // (2, 3, 3) fp32
    float*       out   = (float*)d_out;

    setup_tables<<<(IMG_W + 255) / 256, 256>>>(dispc);

    dim3 block(BX, BY, 1);
    dim3 grid(IMG_W / BX, IMG_H / (BY * PX_PER_THREAD), 1);
    elastic_warp_kernel<<<grid, block>>>(img, out);
}